// round 15
// baseline (speedup 1.0000x reference)
#include <cuda_runtime.h>
#include <cuda_bf16.h>
#include <math.h>
#include <stdint.h>

#define N_NODES 50000
#define N_PAD   (N_NODES + 128)
#define E_RAW   800000
#define E_TOT   850000
#define BN_EPS  1e-5f
#define NEG     0.2f

#define SCAN_B  256
#define SCAN_NB ((N_NODES + SCAN_B - 1) / SCAN_B)   // 196

// ---------------- static device scratch ----------------
__device__ float g_h  [(size_t)N_NODES * 256];          // GEMM output (fp32, agg gather source)
__device__ __nv_bfloat16 g_ah[(size_t)N_PAD * 256];     // A operand hi (bf16)
__device__ __nv_bfloat16 g_al[(size_t)N_PAD * 256];     // A operand lo
__device__ __nv_bfloat16 g_bh[256 * 256];               // W^T hi ([M][K])
__device__ __nv_bfloat16 g_bl[256 * 256];               // W^T lo
__device__ float g_als[N_NODES * 8];
__device__ float g_ald[N_NODES * 8];
__device__ int   g_deg[N_NODES];
__device__ int   g_rowstart[N_NODES + 1];
__device__ int   g_cursor[N_NODES];
__device__ int   g_csr[E_TOT];
__device__ int   g_part[SCAN_NB];
__device__ int   g_boff[SCAN_NB];
__device__ int   g_is64;

// ---------------- helpers ----------------
__device__ __forceinline__ uint32_t smem_u32(const void* p) {
    uint32_t a;
    asm("{ .reg .u64 t; cvta.to.shared.u64 t, %1; cvt.u32.u64 %0, t; }" : "=r"(a) : "l"(p));
    return a;
}
__device__ __forceinline__ void ldsm_x4(uint32_t* r, uint32_t addr) {
    asm volatile("ldmatrix.sync.aligned.m8n8.x4.shared.b16 {%0,%1,%2,%3}, [%4];"
                 : "=r"(r[0]), "=r"(r[1]), "=r"(r[2]), "=r"(r[3]) : "r"(addr));
}
__device__ __forceinline__ void mma_bf16(float* d, const uint32_t* a, const uint32_t* b) {
    asm volatile(
        "mma.sync.aligned.m16n8k16.row.col.f32.bf16.bf16.f32 "
        "{%0,%1,%2,%3}, {%4,%5,%6,%7}, {%8,%9}, {%0,%1,%2,%3};"
        : "+f"(d[0]), "+f"(d[1]), "+f"(d[2]), "+f"(d[3])
        : "r"(a[0]), "r"(a[1]), "r"(a[2]), "r"(a[3]), "r"(b[0]), "r"(b[1]));
}
__device__ __forceinline__ void split_pack(float x, float y, uint32_t& hi, uint32_t& lo) {
    __nv_bfloat16 hx = __float2bfloat16_rn(x);
    __nv_bfloat16 hy = __float2bfloat16_rn(y);
    __nv_bfloat16 lx = __float2bfloat16_rn(x - __bfloat162float(hx));
    __nv_bfloat16 ly = __float2bfloat16_rn(y - __bfloat162float(hy));
    hi = ((uint32_t)__bfloat16_as_ushort(hy) << 16) | __bfloat16_as_ushort(hx);
    lo = ((uint32_t)__bfloat16_as_ushort(ly) << 16) | __bfloat16_as_ushort(lx);
}
#define CP_ASYNC16(sm, gp) \
    asm volatile("cp.async.cg.shared.global [%0], [%1], 16;" :: "r"(sm), "l"(gp) : "memory")
#define CP_COMMIT() asm volatile("cp.async.commit_group;" ::: "memory")
#define CP_WAIT2()  asm volatile("cp.async.wait_group 2;" ::: "memory")
#define CP_WAIT1()  asm volatile("cp.async.wait_group 1;" ::: "memory")
#define CP_WAIT0()  asm volatile("cp.async.wait_group 0;" ::: "memory")

// ---------------- dtype probe ----------------
__global__ void detect_dtype_k(const int* __restrict__ ei32) {
    if (threadIdx.x == 0 && blockIdx.x == 0) {
        int z = 0;
        #pragma unroll
        for (int j = 1; j < 33; j += 2) z |= ei32[j];
        g_is64 = (z == 0) ? 1 : 0;
    }
}
__device__ __forceinline__ int load_edge(const void* ei, int is64, long long idx) {
    if (is64) return (int)((const long long*)ei)[idx];
    return ((const int*)ei)[idx];
}

// ---------------- operand conversion ----------------
__global__ void conv_x_k(const float* __restrict__ x) {
    int t = blockIdx.x * blockDim.x + threadIdx.x;
    int total = N_NODES * 128 / 4;
    if (t >= total) return;
    float4 v = *(const float4*)(x + (size_t)t * 4);
    uint32_t h0, l0, h1, l1;
    split_pack(v.x, v.y, h0, l0);
    split_pack(v.z, v.w, h1, l1);
    *(uint2*)(g_ah + (size_t)t * 4) = make_uint2(h0, h1);
    *(uint2*)(g_al + (size_t)t * 4) = make_uint2(l0, l1);
}
__global__ void conv_w_k(const float* __restrict__ W, int K, int M) {
    int t = blockIdx.x * blockDim.x + threadIdx.x;
    if (t >= K * M) return;
    int m = t / K, k = t - m * K;
    float v = W[(size_t)k * M + m];
    __nv_bfloat16 h = __float2bfloat16_rn(v);
    g_bh[t] = h;
    g_bl[t] = __float2bfloat16_rn(v - __bfloat162float(h));
}

// ---------------- CSR build ----------------
__global__ void zero_deg_k() {
    int i = blockIdx.x * blockDim.x + threadIdx.x;
    if (i < N_NODES) g_deg[i] = 0;
}
__global__ void count_deg_k(const void* __restrict__ ei) {
    int i = blockIdx.x * blockDim.x + threadIdx.x;
    if (i >= E_TOT) return;
    int is64 = g_is64;
    int dst = (i < E_RAW) ? load_edge(ei, is64, (long long)E_RAW + i) : (i - E_RAW);
    atomicAdd(&g_deg[dst], 1);
}
__global__ void scanA_k() {
    __shared__ int sh[SCAN_B];
    int i = blockIdx.x * SCAN_B + threadIdx.x;
    sh[threadIdx.x] = (i < N_NODES) ? g_deg[i] : 0;
    __syncthreads();
    #pragma unroll
    for (int off = SCAN_B / 2; off > 0; off >>= 1) {
        if (threadIdx.x < off) sh[threadIdx.x] += sh[threadIdx.x + off];
        __syncthreads();
    }
    if (threadIdx.x == 0) g_part[blockIdx.x] = sh[0];
}
__global__ void scanB_k() {
    __shared__ int sh[SCAN_B];
    int tid = threadIdx.x;
    int v = (tid < SCAN_NB) ? g_part[tid] : 0;
    sh[tid] = v;
    __syncthreads();
    #pragma unroll
    for (int off = 1; off < SCAN_B; off <<= 1) {
        int t = (tid >= off) ? sh[tid - off] : 0;
        __syncthreads();
        sh[tid] += t;
        __syncthreads();
    }
    if (tid < SCAN_NB) g_boff[tid] = sh[tid] - v;
    if (tid == 0) g_rowstart[0] = 0;
}
__global__ void scanC_k() {
    __shared__ int sh[SCAN_B];
    int tid = threadIdx.x;
    int i = blockIdx.x * SCAN_B + tid;
    int v = (i < N_NODES) ? g_deg[i] : 0;
    sh[tid] = v;
    __syncthreads();
    #pragma unroll
    for (int off = 1; off < SCAN_B; off <<= 1) {
        int t = (tid >= off) ? sh[tid - off] : 0;
        __syncthreads();
        sh[tid] += t;
        __syncthreads();
    }
    if (i < N_NODES) {
        int incl = sh[tid] + g_boff[blockIdx.x];
        g_rowstart[i + 1] = incl;
        g_cursor[i]       = incl - v;
    }
}
__global__ void fill_csr_k(const void* __restrict__ ei) {
    int i = blockIdx.x * blockDim.x + threadIdx.x;
    if (i >= E_TOT) return;
    int is64 = g_is64;
    int src, dst;
    if (i < E_RAW) {
        src = load_edge(ei, is64, i);
        dst = load_edge(ei, is64, (long long)E_RAW + i);
    } else {
        src = dst = i - E_RAW;
    }
    int pos = atomicAdd(&g_cursor[dst], 1);
    g_csr[pos] = src;
}

// ---------------- tensor-core GEMM: g_h[N,M_out] = (Ah+Al) @ (Bh+Bl)^T ----------------
// Pre-split bf16 operands in gmem. CTA tile 128x128, 8 warps (4m x 2n), BK=16,
// 3-stage cp.async pipeline (prefetch distance 2), ONE __syncthreads per chunk.
// Safety of single barrier: a thread passes the iter-c barrier only after its
// iter-(c-1) mma issued, which requires ldmatrix writeback (= smem read done);
// buffer (c%3) is only overwritten by chunk c+3, issued after the iter-(c+1)
// barrier -> no read/write hazard.
#define PADW   24
#define ARRSZ  (128 * PADW)          // halves per array per stage
#define STAGEB (4 * ARRSZ * 2)       // bytes per stage (24576)
#define GSMEM  (3 * STAGEB)          // 73728 B dynamic

__global__ void __launch_bounds__(256, 2)
mma_gemm_k(int K, int M_out) {
    extern __shared__ __nv_bfloat16 SB[];

    int tid  = threadIdx.x;
    int lane = tid & 31, wid = tid >> 5;
    int wm = (wid & 3) * 32, wn = (wid >> 2) * 64;
    int g = lane >> 2, tig = lane & 3;
    int row0 = blockIdx.y * 128, col0 = blockIdx.x * 128;

    int a_r = lane & 15;
    int a_k = (lane >> 4) * 8;
    int b_r = ((lane >> 4) & 1) * 8 + (lane & 7);
    int b_k = ((lane >> 3) & 1) * 8;

    uint32_t sb0 = smem_u32(SB);
    const uint32_t LOOFF = ARRSZ * 2;        // Ah->Al / Bh->Bl
    const uint32_t BOFF  = 2 * ARRSZ * 2;    // Ah->Bh

    int sr = tid >> 1, sc = (tid & 1) * 8;
    const __nv_bfloat16* gAh = g_ah + (size_t)(row0 + sr) * K + sc;
    const __nv_bfloat16* gAl = g_al + (size_t)(row0 + sr) * K + sc;
    const __nv_bfloat16* gBh = g_bh + (size_t)(col0 + sr) * K + sc;
    const __nv_bfloat16* gBl = g_bl + (size_t)(col0 + sr) * K + sc;
    uint32_t s_stage = sb0 + (uint32_t)sr * (PADW * 2) + (uint32_t)sc * 2;

    float acc[2][8][4];
    #pragma unroll
    for (int i = 0; i < 2; i++)
        #pragma unroll
        for (int j = 0; j < 8; j++)
            #pragma unroll
            for (int q = 0; q < 4; q++) acc[i][j][q] = 0.f;

    const int nch = K >> 4;   // >= 8 always

    // preload chunks 0,1,2 into stages 0,1,2 (one commit group per chunk)
    #pragma unroll
    for (int s = 0; s < 3; s++) {
        int kk = s << 4;
        uint32_t sd = s_stage + (uint32_t)s * STAGEB;
        CP_ASYNC16(sd,                gAh + kk);
        CP_ASYNC16(sd + LOOFF,        gAl + kk);
        CP_ASYNC16(sd + BOFF,         gBh + kk);
        CP_ASYNC16(sd + BOFF + LOOFF, gBl + kk);
        CP_COMMIT();
    }

    int st = 0;                         // stage of current chunk
    int pst = 0;                        // stage for next prefetch target (chunk c+3)
    for (int c = 0; c < nch; c++) {
        // prefetch chunk c+3 into stage (c+3)%3 == c%3?  No: (c+3)%3 == c%3 — that's
        // the CURRENT stage; must issue AFTER this iteration's barrier. Do it below.
        int rem = nch - 1 - c;          // chunks still in flight after this one
        if (rem >= 2) CP_WAIT2(); else if (rem == 1) CP_WAIT1(); else CP_WAIT0();
        __syncthreads();

        // issue prefetch for chunk c+3 into this same stage's successor slot:
        // stage reused by chunk c+3 is (c+3)%3; it currently holds chunk c... no —
        // stages hold chunks c (st), c+1, c+2. Chunk c+3 must go into stage st,
        // but st is being read THIS iteration. Defer: issue at next iteration.
        if (c >= 1 && c + 2 < nch) {
            // now safe: stage pst held chunk c-1, fully consumed before this barrier
            int kk = (c + 2) << 4;
            uint32_t sd = s_stage + (uint32_t)pst * STAGEB;
            CP_ASYNC16(sd,                gAh + kk);
            CP_ASYNC16(sd + LOOFF,        gAl + kk);
            CP_ASYNC16(sd + BOFF,         gBh + kk);
            CP_ASYNC16(sd + BOFF + LOOFF, gBl + kk);
            CP_COMMIT();
            pst = (pst + 1 == 3) ? 0 : pst + 1;
        }

        uint32_t ahb = sb0 + (uint32_t)st * STAGEB;
        uint32_t bhb = ahb + BOFF;
        uint32_t afh[2][4], afl[2][4];
        #pragma unroll
        for (int i = 0; i < 2; i++) {
            uint32_t ra = ahb + (uint32_t)(wm + 16 * i + a_r) * (PADW * 2) + (uint32_t)a_k * 2;
            ldsm_x4(afh[i], ra);
            ldsm_x4(afl[i], ra + LOOFF);
        }
        #pragma unroll
        for (int jj = 0; jj < 8; jj += 2) {
            uint32_t rb = bhb + (uint32_t)(wn + 8 * jj + b_r) * (PADW * 2) + (uint32_t)b_k * 2;
            uint32_t bh4[4], bl4[4];
            ldsm_x4(bh4, rb);
            ldsm_x4(bl4, rb + LOOFF);
            #pragma unroll
            for (int i = 0; i < 2; i++) {
                mma_bf16(acc[i][jj],     afh[i], bh4);
                mma_bf16(acc[i][jj],     afh[i], bl4);
                mma_bf16(acc[i][jj],     afl[i], bh4);
                mma_bf16(acc[i][jj + 1], afh[i], bh4 + 2);
                mma_bf16(acc[i][jj + 1], afh[i], bl4 + 2);
                mma_bf16(acc[i][jj + 1], afl[i], bh4 + 2);
            }
        }
        st = (st + 1 == 3) ? 0 : st + 1;
    }

    #pragma unroll
    for (int i = 0; i < 2; i++) {
        int r0 = row0 + wm + 16 * i + g;
        #pragma unroll
        for (int j = 0; j < 8; j++) {
            int cidx = col0 + wn + 8 * j + 2 * tig;
            if (r0 < N_NODES)
                *(float2*)(g_h + (size_t)r0 * M_out + cidx) = make_float2(acc[i][j][0], acc[i][j][1]);
            if (r0 + 8 < N_NODES)
                *(float2*)(g_h + (size_t)(r0 + 8) * M_out + cidx) = make_float2(acc[i][j][2], acc[i][j][3]);
        }
    }
}

// ---------------- attention logits ----------------
template <int F, int H>
__global__ void att_dots_k(const float* __restrict__ asrc, const float* __restrict__ adst) {
    int gid  = blockIdx.x * blockDim.x + threadIdx.x;
    int node = gid >> 5, lane = gid & 31;
    if (node >= N_NODES) return;
    constexpr int PER = F / 32, C = F / H, GROUP = C / PER;
    int cb = lane * PER;
    float ps = 0.f, pd = 0.f;
    #pragma unroll
    for (int j = 0; j < PER; j++) {
        float v = g_h[(size_t)node * F + cb + j];
        ps += v * asrc[cb + j];
        pd += v * adst[cb + j];
    }
    #pragma unroll
    for (int off = GROUP >> 1; off > 0; off >>= 1) {
        ps += __shfl_xor_sync(0xffffffffu, ps, off);
        pd += __shfl_xor_sync(0xffffffffu, pd, off);
    }
    if ((lane & (GROUP - 1)) == 0) {
        int h_ = cb / C;
        g_als[node * H + h_] = ps;
        g_ald[node * H + h_] = pd;
    }
}

// ---------------- fused softmax + aggregation (+ bias/BN/ELU), single pass ----------------
template <int F, int H, bool DO_BN, int OUTMODE>
__global__ void agg_k(const float* __restrict__ bias,
                      const float* __restrict__ gamma, const float* __restrict__ beta,
                      const float* __restrict__ mean,  const float* __restrict__ var,
                      float* __restrict__ out) {
    int gid  = blockIdx.x * blockDim.x + threadIdx.x;
    int node = gid >> 5, lane = gid & 31;
    if (node >= N_NODES) return;
    constexpr int PER = F / 32, C = F / H;
    int cb = lane * PER;
    int h_ = cb / C;
    float aldv = g_ald[node * H + h_];
    int s0 = g_rowstart[node], s1 = g_rowstart[node + 1];

    float acc[PER];
    #pragma unroll
    for (int j = 0; j < PER; j++) acc[j] = 0.f;
    float den = 0.f;

    for (int e = s0; e < s1; e++) {
        int s = g_csr[e];
        float v = g_als[s * H + h_] + aldv;
        v = v > 0.f ? v : NEG * v;
        float ex = __expf(v);
        den += ex;
        const float4* hp = (const float4*)(g_h + (size_t)s * F + cb);
        #pragma unroll
        for (int q = 0; q < PER / 4; q++) {
            float4 t = hp[q];
            acc[4 * q + 0] += ex * t.x;
            acc[4 * q + 1] += ex * t.y;
            acc[4 * q + 2] += ex * t.z;
            acc[4 * q + 3] += ex * t.w;
        }
    }

    float inv = 1.f / den;
    float res[PER];
    #pragma unroll
    for (int j = 0; j < PER; j++) {
        int c = cb + j;
        float r = acc[j] * inv + bias[c];
        if constexpr (DO_BN) {
            r = (r - mean[c]) * rsqrtf(var[c] + BN_EPS) * gamma[c] + beta[c];
            r = r > 0.f ? r : expm1f(r);   // ELU
        }
        res[j] = r;
    }
    if constexpr (OUTMODE == 0) {
        uint32_t hw[4], lw[4];
        #pragma unroll
        for (int q = 0; q < PER / 2; q++)
            split_pack(res[2 * q], res[2 * q + 1], hw[q], lw[q]);
        *(uint4*)(g_ah + (size_t)node * F + cb) = make_uint4(hw[0], hw[1], hw[2], hw[3]);
        *(uint4*)(g_al + (size_t)node * F + cb) = make_uint4(lw[0], lw[1], lw[2], lw[3]);
    } else {
        float* dstp = out + (size_t)node * F + cb;
        #pragma unroll
        for (int q = 0; q < PER / 4; q++)
            *(float4*)(dstp + 4 * q) =
                make_float4(res[4 * q], res[4 * q + 1], res[4 * q + 2], res[4 * q + 3]);
    }
}

// ---------------- launcher ----------------
extern "C" void kernel_launch(void* const* d_in, const int* in_sizes, int n_in,
                              void* d_out, int out_size) {
    const float* x   = (const float*)d_in[0];
    const void*  ei  = d_in[1];
    const float* W1  = (const float*)d_in[2];
    const float* as1 = (const float*)d_in[3];
    const float* ad1 = (const float*)d_in[4];
    const float* b1  = (const float*)d_in[5];
    const float* g1  = (const float*)d_in[6];
    const float* be1 = (const float*)d_in[7];
    const float* m1  = (const float*)d_in[8];
    const float* v1  = (const float*)d_in[9];
    const float* W2  = (const float*)d_in[10];
    const float* as2 = (const float*)d_in[11];
    const float* ad2 = (const float*)d_in[12];
    const float* b2  = (const float*)d_in[13];
    const float* g2  = (const float*)d_in[14];
    const float* be2 = (const float*)d_in[15];
    const float* m2  = (const float*)d_in[16];
    const float* v2  = (const float*)d_in[17];
    const float* W3  = (const float*)d_in[18];
    const float* as3 = (const float*)d_in[19];
    const float* ad3 = (const float*)d_in[20];
    const float* b3  = (const float*)d_in[21];
    float* out = (float*)d_out;

    // host-side attribute; eager + idempotent (not a graph node)
    cudaFuncSetAttribute(mma_gemm_k, cudaFuncAttributeMaxDynamicSharedMemorySize, GSMEM);

    const int EB = (E_TOT + 255) / 256;
    const int NB = (N_NODES + 255) / 256;
    const int WARP_GRID = (N_NODES * 32 + 255) / 256;
    const int RT = (N_NODES + 127) / 128;           // 391 row tiles
    const int CXB = (N_NODES * 128 / 4 + 255) / 256;

    detect_dtype_k<<<1, 32>>>((const int*)ei);
    conv_x_k<<<CXB, 256>>>(x);
    conv_w_k<<<(128 * 256 + 255) / 256, 256>>>(W1, 128, 256);
    mma_gemm_k<<<dim3(2, RT), 256, GSMEM>>>(128, 256);     // slot #4 for ncu

    zero_deg_k<<<NB, 256>>>();
    count_deg_k<<<EB, 256>>>(ei);
    scanA_k<<<SCAN_NB, SCAN_B>>>();
    scanB_k<<<1, SCAN_B>>>();
    scanC_k<<<SCAN_NB, SCAN_B>>>();
    fill_csr_k<<<EB, 256>>>(ei);

    att_dots_k<256, 8><<<WARP_GRID, 256>>>(as1, ad1);
    agg_k<256, 8, true, 0><<<WARP_GRID, 256>>>(b1, g1, be1, m1, v1, nullptr);

    conv_w_k<<<(256 * 256 + 255) / 256, 256>>>(W2, 256, 256);
    mma_gemm_k<<<dim3(2, RT), 256, GSMEM>>>(256, 256);
    att_dots_k<256, 8><<<WARP_GRID, 256>>>(as2, ad2);
    agg_k<256, 8, true, 0><<<WARP_GRID, 256>>>(b2, g2, be2, m2, v2, nullptr);

    conv_w_k<<<(256 * 128 + 255) / 256, 256>>>(W3, 256, 128);
    mma_gemm_k<<<dim3(1, RT), 256, GSMEM>>>(256, 128);
    att_dots_k<128, 1><<<WARP_GRID, 256>>>(as3, ad3);
    agg_k<128, 1, false, 1><<<WARP_GRID, 256>>>(b3, nullptr, nullptr, nullptr, nullptr, out);

    (void)in_sizes; (void)n_in; (void)out_size;
}